// round 1
// baseline (speedup 1.0000x reference)
#include <cuda_runtime.h>
#include <math.h>

// Problem constants (fixed by the dataset)
#define DIM 512
#define MARGIN 1.0f
#define RULE_WEIGHT 0.5f

#define MAX_B   1024
#define MAX_NEG 8192

// Scratch (allocation-free rule: __device__ globals)
__device__ float g_dpos[MAX_B];
__device__ float g_dneg[MAX_NEG];
__device__ float g_rule[MAX_B];

__device__ __forceinline__ float warp_red(float v) {
#pragma unroll
    for (int o = 16; o; o >>= 1) v += __shfl_xor_sync(0xffffffffu, v, o);
    return v;
}

// TransH distance with he/te already register-resident (warp-collective).
// d = || (he - te + re) - c*w ||,  c = (he.w - te.w)/(w.w)
__device__ __forceinline__ float dist_from_regs(
    const float4 he[4], const float4 te[4],
    const float* __restrict__ rel, const float* __restrict__ nv,
    int r, int lane)
{
    const float4* w4  = reinterpret_cast<const float4*>(nv  + (size_t)r * DIM);
    const float4* re4 = reinterpret_cast<const float4*>(rel + (size_t)r * DIM);
    float4 w[4], re[4];
    float ww = 0.f, hw = 0.f, tw = 0.f;
#pragma unroll
    for (int i = 0; i < 4; i++) {
        w[i]  = w4[lane + 32 * i];
        re[i] = re4[lane + 32 * i];
        ww += w[i].x * w[i].x + w[i].y * w[i].y + w[i].z * w[i].z + w[i].w * w[i].w;
        hw += he[i].x * w[i].x + he[i].y * w[i].y + he[i].z * w[i].z + he[i].w * w[i].w;
        tw += te[i].x * w[i].x + te[i].y * w[i].y + te[i].z * w[i].z + te[i].w * w[i].w;
    }
    ww = warp_red(ww);
    hw = warp_red(hw);
    tw = warp_red(tw);
    float c = (hw - tw) / ww;
    float ss = 0.f;
#pragma unroll
    for (int i = 0; i < 4; i++) {
        float dx = he[i].x - te[i].x + re[i].x - c * w[i].x;
        float dy = he[i].y - te[i].y + re[i].y - c * w[i].y;
        float dz = he[i].z - te[i].z + re[i].z - c * w[i].z;
        float dw = he[i].w - te[i].w + re[i].w - c * w[i].w;
        ss += dx * dx + dy * dy + dz * dz + dw * dw;
    }
    ss = warp_red(ss);
    return sqrtf(ss);
}

// One warp per distance task. Tasks [0, B) = unique pos triples (also handle
// the rule terms for that triple, reusing register-resident he/te). Tasks
// [B, B+NEG) = neg triples.
__global__ void __launch_bounds__(256)
dist_kernel(const int* __restrict__ pos, const int* __restrict__ neg,
            const int* __restrict__ rr1, const int* __restrict__ rr2,
            const float* __restrict__ rconf,
            const float* __restrict__ ent, const float* __restrict__ rel,
            const float* __restrict__ nv,
            int B, int NEG, int NR)
{
    int gw   = (blockIdx.x * blockDim.x + threadIdx.x) >> 5;
    int lane = threadIdx.x & 31;

    int h, r, t;
    bool is_pos = (gw < B);
    if (is_pos) {
        h = pos[3 * gw]; r = pos[3 * gw + 1]; t = pos[3 * gw + 2];
    } else {
        int k = gw - B;
        if (k >= NEG) return;
        h = neg[3 * k]; r = neg[3 * k + 1]; t = neg[3 * k + 2];
    }

    const float4* he4 = reinterpret_cast<const float4*>(ent + (size_t)h * DIM);
    const float4* te4 = reinterpret_cast<const float4*>(ent + (size_t)t * DIM);
    float4 he[4], te[4];
#pragma unroll
    for (int i = 0; i < 4; i++) {
        he[i] = he4[lane + 32 * i];
        te[i] = te4[lane + 32 * i];
    }

    float d = dist_from_regs(he, te, rel, nv, r, lane);

    if (is_pos) {
        // Rule terms: only rules with rule_r1[j] == r contribute (mask==1);
        // everything else is an exact zero in the reference, so skip it.
        float racc = 0.f;
        for (int j = 0; j < NR; j++) {
            if (rr1[j] == r)
                racc += rconf[j] * dist_from_regs(he, te, rel, nv, rr2[j], lane);
        }
        if (lane == 0) { g_dpos[gw] = d; g_rule[gw] = racc; }
    } else {
        if (lane == 0) g_dneg[gw - B] = d;
    }
}

// Final reduction: basic margin loss (pos repeat-interleaved by ratio) + rule loss.
__global__ void __launch_bounds__(256)
reduce_kernel(float* __restrict__ out, int B, int NEG)
{
    __shared__ float sb[256];
    __shared__ float sr[256];
    int tid = threadIdx.x;
    int ratio = NEG / B;

    float acc = 0.f;
    for (int k = tid; k < NEG; k += 256) {
        float v = MARGIN + g_dpos[k / ratio] - g_dneg[k];
        acc += (v > 0.f) ? v : 0.f;
    }
    float racc = 0.f;
    for (int i = tid; i < B; i += 256) racc += g_rule[i];

    sb[tid] = acc; sr[tid] = racc;
    __syncthreads();
    for (int s = 128; s; s >>= 1) {
        if (tid < s) { sb[tid] += sb[tid + s]; sr[tid] += sr[tid + s]; }
        __syncthreads();
    }
    if (tid == 0)
        out[0] = sb[0] / (float)NEG + RULE_WEIGHT * sr[0];
}

extern "C" void kernel_launch(void* const* d_in, const int* in_sizes, int n_in,
                              void* d_out, int out_size)
{
    const int*   pos   = (const int*)d_in[0];     // [B,3]
    const int*   neg   = (const int*)d_in[1];     // [B*ratio,3]
    const int*   rr1   = (const int*)d_in[2];     // [NR]
    const int*   rr2   = (const int*)d_in[3];     // [NR]
    const float* rconf = (const float*)d_in[4];   // [NR]
    const float* ent   = (const float*)d_in[5];   // [NUM_ENT, DIM]
    const float* rel   = (const float*)d_in[6];   // [NUM_REL, DIM]
    const float* nv    = (const float*)d_in[7];   // [NUM_REL, DIM]

    int B   = in_sizes[0] / 3;
    int NEG = in_sizes[1] / 3;
    int NR  = in_sizes[2];

    int totalWarps = B + NEG;
    int blocks = (totalWarps * 32 + 255) / 256;

    dist_kernel<<<blocks, 256>>>(pos, neg, rr1, rr2, rconf, ent, rel, nv, B, NEG, NR);
    reduce_kernel<<<1, 256>>>((float*)d_out, B, NEG);
}